// round 1
// baseline (speedup 1.0000x reference)
#include <cuda_runtime.h>
#include <cuda_bf16.h>

// CensoredLoss: outputs [B, T, V-1] f32, targets [B, T, V] f32, T=512, V=5.
// loss = sum_{b,t} [ tgt0*log(1 - sum(out) + EPS) + sum_v tgt_{v+1}*log(out_v + EPS) ]
// (mask is implicit: masked rows have all-zero targets -> zero contribution)
// count = sum_b (1 + max{t : sum_v targets[b,t,v] > 0})  (0 if none)
// result = count > 0 ? -loss/count : 0

#define T_DIM 512
#define V_DIM 5
#define EPSF 1e-8f
#define NTHREADS 512

__device__ double g_loss;
__device__ unsigned long long g_count;

__global__ void cl_init_kernel() {
    g_loss = 0.0;
    g_count = 0ULL;
}

__global__ __launch_bounds__(NTHREADS, 4)
void cl_main_kernel(const float* __restrict__ outputs,
                    const float* __restrict__ targets)
{
    __shared__ float s_tgt[T_DIM * V_DIM];       // 10240 B, one row of targets
    __shared__ float s_sum[NTHREADS / 32];
    __shared__ int   s_max[NTHREADS / 32];

    const int b   = blockIdx.x;
    const int tid = threadIdx.x;

    // Stage this row's targets via fully-coalesced float4 loads.
    // Row base byte offset = b * 512 * 5 * 4 = b * 10240 -> 16B aligned.
    const float4* tg4 = reinterpret_cast<const float4*>(
        targets + (size_t)b * (T_DIM * V_DIM));
    float4* s4 = reinterpret_cast<float4*>(s_tgt);
    #pragma unroll
    for (int i = tid; i < (T_DIM * V_DIM) / 4; i += NTHREADS)
        s4[i] = tg4[i];
    __syncthreads();

    const int t = tid;  // one timestep per thread

    // outputs record is exactly a float4 (4 floats, 16B aligned).
    const float4 o = reinterpret_cast<const float4*>(outputs)[(size_t)b * T_DIM + t];

    // 5-float target record from SMEM: bank = (5*lane + j) mod 32, conflict-free.
    const float t0 = s_tgt[t * 5 + 0];
    const float t1 = s_tgt[t * 5 + 1];
    const float t2 = s_tgt[t * 5 + 2];
    const float t3 = s_tgt[t * 5 + 3];
    const float t4 = s_tgt[t * 5 + 4];

    const float censor = 1.0f - (o.x + o.y + o.z + o.w);

    float c = t0 * __logf(censor + EPSF)
            + t1 * __logf(o.x + EPSF)
            + t2 * __logf(o.y + EPSF)
            + t3 * __logf(o.z + EPSF)
            + t4 * __logf(o.w + EPSF);

    // per_t > 0  (targets are nonnegative; zero-padded region is exactly 0)
    int last = ((t0 + t1 + t2 + t3 + t4) > 0.0f) ? t : -1;

    // Warp reduction
    #pragma unroll
    for (int off = 16; off > 0; off >>= 1) {
        c    += __shfl_down_sync(0xffffffffu, c, off);
        last  = max(last, __shfl_down_sync(0xffffffffu, last, off));
    }
    if ((tid & 31) == 0) {
        s_sum[tid >> 5] = c;
        s_max[tid >> 5] = last;
    }
    __syncthreads();

    // Final reduce across 16 warps (lanes 0..15 of warp 0)
    if (tid < NTHREADS / 32) {
        c    = s_sum[tid];
        last = s_max[tid];
        #pragma unroll
        for (int off = (NTHREADS / 64); off > 0; off >>= 1) {
            c    += __shfl_down_sync(0xffffu, c, off);
            last  = max(last, __shfl_down_sync(0xffffu, last, off));
        }
        if (tid == 0) {
            atomicAdd(&g_loss, (double)c);
            atomicAdd(&g_count, (unsigned long long)(last + 1));
        }
    }
}

__global__ void cl_final_kernel(float* __restrict__ out) {
    const double loss = g_loss;
    const unsigned long long cnt = g_count;
    out[0] = (cnt > 0ULL) ? (float)(-loss / (double)cnt) : 0.0f;
}

extern "C" void kernel_launch(void* const* d_in, const int* in_sizes, int n_in,
                              void* d_out, int out_size)
{
    const float* outputs = (const float*)d_in[0];
    const float* targets = (const float*)d_in[1];
    float* out = (float*)d_out;

    const int B = in_sizes[1] / (T_DIM * V_DIM);   // 16384

    cl_init_kernel<<<1, 1>>>();
    cl_main_kernel<<<B, NTHREADS>>>(outputs, targets);
    cl_final_kernel<<<1, 1>>>(out);
}